// round 17
// baseline (speedup 1.0000x reference)
#include <cuda_runtime.h>
#include <cuda_fp16.h>
#include <cstdint>

#define BB 8
#define NN 2048
#define DD 512
#define CC 4096
#define MM (BB*NN)   // 16384

// screen-kernel tiling
#define Bb_M 128
#define Bb_N 128
#define Bb_K 128                  // k-depth per B chunk (2 x 64-k blocks)
#define NCT (CC/Bb_N)             // 32 c-tiles
#define NKC (DD/Bb_K)             // 4 k-chunks per c-tile
#define NQ  (NCT*NKC)             // 128 chunks
#define KB_BYTES 16384            // one 64-k block: 128 rows x 128B
#define BSTAGE_BYTES (2*KB_BYTES) // 32KB B chunk (k=128)
#define A_BYTES  (8*KB_BYTES)     // resident A: 128 x 512 fp16 = 128KB
#define SMEM_DYN (A_BYTES + 2*BSTAGE_BYTES)   // 192KB
#define SCR_THR 256               // 8 warps: 2 warp_m x 4 warp_n, 64x32 tiles

// implicit-GEMM smem: 2 stages x 4 tiles x 16KB
#define SMEM_IMPL (2*4*KB_BYTES)  // 131072

// ---------------- scratch ----------------
__device__ float g_implicit[CC * DD];
__device__ float g_halfnorm[CC];
__device__ int   g_cand[MM * 4];
__device__ float g_commit[MM];
__device__ __align__(16) char g_xh_sw[(size_t)MM * DD * 2];  // [mtile][kb][row][seg^]
__device__ __align__(16) char g_ch_sw[(size_t)CC * DD * 2];  // [chunk][kb2][row][seg^]
__device__ __half g_cbl0[CC * DD];
__device__ __half g_cbl1[CC * DD];
__device__ __half g_wl0[DD * DD];
__device__ __half g_wl1[DD * DD];

// =============================== helpers ===================================
__device__ __forceinline__ uint32_t smem_u32(const void* p) {
    return (uint32_t)__cvta_generic_to_shared(p);
}
__device__ __forceinline__ void cp16(uint32_t s, const void* g) {
    asm volatile("cp.async.cg.shared.global [%0], [%1], 16;" :: "r"(s), "l"(g));
}
#define CP_COMMIT() asm volatile("cp.async.commit_group;")
#define CP_WAIT1()  asm volatile("cp.async.wait_group 1;")
#define LDM4(r0,r1,r2,r3,addr) \
    asm volatile("ldmatrix.sync.aligned.m8n8.x4.shared.b16 {%0,%1,%2,%3},[%4];" \
                 : "=r"(r0),"=r"(r1),"=r"(r2),"=r"(r3) : "r"(addr))
#define MMA16816(c,a,b) \
    asm volatile("mma.sync.aligned.m16n8k16.row.col.f32.f16.f16.f32 " \
                 "{%0,%1,%2,%3},{%4,%5,%6,%7},{%8,%9},{%0,%1,%2,%3};" \
                 : "+f"((c)[0]),"+f"((c)[1]),"+f"((c)[2]),"+f"((c)[3]) \
                 : "r"((a)[0]),"r"((a)[1]),"r"((a)[2]),"r"((a)[3]), \
                   "r"((b)[0]),"r"((b)[1]))

// mbarrier ops
__device__ __forceinline__ void mbar_init(uint32_t a, uint32_t cnt) {
    asm volatile("mbarrier.init.shared.b64 [%0], %1;" :: "r"(a), "r"(cnt) : "memory");
}
__device__ __forceinline__ void mbar_expect_tx(uint32_t a, uint32_t bytes) {
    asm volatile("mbarrier.arrive.expect_tx.shared.b64 _, [%0], %1;" :: "r"(a), "r"(bytes) : "memory");
}
__device__ __forceinline__ void mbar_wait(uint32_t a, uint32_t phase) {
    uint32_t done;
    asm volatile("{\n\t.reg .pred p;\n\t"
                 "mbarrier.try_wait.parity.acquire.cta.shared::cta.b64 p, [%1], %2;\n\t"
                 "selp.b32 %0, 1, 0, p;\n\t}"
                 : "=r"(done) : "r"(a), "r"(phase) : "memory");
    if (!done) {
        asm volatile("{\n\t.reg .pred P1;\n\t"
                     "W_%=:\n\t"
                     "mbarrier.try_wait.parity.acquire.cta.shared::cta.b64 P1, [%0], %1, 0x989680;\n\t"
                     "@P1 bra.uni D_%=;\n\t"
                     "bra.uni W_%=;\n\t"
                     "D_%=:\n\t}"
                     :: "r"(a), "r"(phase) : "memory");
    }
}
__device__ __forceinline__ void bulk_copy(uint32_t dst, const void* src,
                                          uint32_t bytes, uint32_t mbar) {
    asm volatile("cp.async.bulk.shared::cta.global.mbarrier::complete_tx::bytes "
                 "[%0], [%1], %2, [%3];"
                 :: "r"(dst), "l"(src), "r"(bytes), "r"(mbar) : "memory");
}

__device__ __forceinline__ uint32_t fkey(float f) {
    uint32_t u = __float_as_uint(f);
    uint32_t m = (u & 0x80000000u) ? 0xFFFFFFFFu : 0x80000000u;
    return u ^ m;
}
__device__ __forceinline__ void ins2u(uint32_t v, uint32_t& b0, uint32_t& b1) {
    uint32_t m0 = max(b0, v);
    b0 = min(b0, v);
    b1 = min(b1, m0);
}
__device__ __forceinline__ void ins4u(uint32_t v, uint32_t& b0, uint32_t& b1,
                                      uint32_t& b2, uint32_t& b3) {
    uint32_t m0 = max(b0, v); b0 = min(b0, v);
    uint32_t m1 = max(b1, m0); b1 = min(b1, m0);
    uint32_t m2 = max(b2, m1); b2 = min(b2, m1);
    b3 = min(b3, m2);
}

// ===========================================================================
// Kernel 1: k_prep_all — one warp per row.
// ===========================================================================
__global__ __launch_bounds__(256) void k_prep_all(const float* __restrict__ x,
                                                  const float* __restrict__ cb,
                                                  const float* __restrict__ Wm) {
    const int warp = threadIdx.x >> 5, lane = threadIdx.x & 31;
    const int row = blockIdx.x * 8 + warp;

    if (row < MM) {
        const int mtile = row >> 7, lrow = row & 127;
        const float4* sr = (const float4*)(x + (size_t)row * DD);
        char* dbase = g_xh_sw + (size_t)mtile * A_BYTES;
#pragma unroll
        for (int it = 0; it < 2; it++) {
            int g16 = lane + 32 * it;          // 0..63
            int kb = g16 >> 3, seg8 = g16 & 7;
            float4 v0 = sr[g16 * 2 + 0];
            float4 v1 = sr[g16 * 2 + 1];
            __half L[8] = {__float2half_rn(v0.x), __float2half_rn(v0.y),
                           __float2half_rn(v0.z), __float2half_rn(v0.w),
                           __float2half_rn(v1.x), __float2half_rn(v1.y),
                           __float2half_rn(v1.z), __float2half_rn(v1.w)};
            size_t off = (size_t)kb * KB_BYTES + lrow * 128 + ((seg8 ^ (lrow & 7)) << 4);
            *(uint4*)(dbase + off) = *(uint4*)L;
        }
    } else {
        const float* src;
        __half *d0, *d1;
        if (row < MM + CC) {
            int r = row - MM;
            src = cb + (size_t)r * DD;
            d0 = g_cbl0 + (size_t)r * DD;
            d1 = g_cbl1 + (size_t)r * DD;
        } else {
            int r = row - MM - CC;
            src = Wm + (size_t)r * DD;
            d0 = g_wl0 + (size_t)r * DD;
            d1 = g_wl1 + (size_t)r * DD;
        }
        const float4* sr = (const float4*)src;
#pragma unroll
        for (int t = 0; t < 4; t++) {
            float4 v = sr[lane + 32 * t];
            float vv[4] = {v.x, v.y, v.z, v.w};
            __half L0[4], L1[4];
#pragma unroll
            for (int c = 0; c < 4; c++) {
                __half h0 = __float2half_rn(vv[c]);
                float r2 = vv[c] - __half2float(h0);
                L0[c] = h0;
                L1[c] = __float2half_rn(r2);
            }
            *(uint2*)(d0 + 4 * (lane + 32 * t)) = *(uint2*)L0;
            *(uint2*)(d1 + 4 * (lane + 32 * t)) = *(uint2*)L1;
        }
    }
}

// ===========================================================================
// Kernel 2: implicit = codebook @ W^T via fp16 2-limb 3-product HMMA.
// ===========================================================================
__device__ __forceinline__ void issue_impl(uint32_t st, int m0, int n0, int kc, int tid) {
#pragma unroll
    for (int t = 0; t < 16; t++) {
        const int tile = t >> 2;
        const int r = (t & 3) * 32 + (tid >> 3);
        const int seg = tid & 7;
        const __half* src;
        if (tile == 0)      src = g_cbl0 + (size_t)(m0 + r) * DD;
        else if (tile == 1) src = g_cbl1 + (size_t)(m0 + r) * DD;
        else if (tile == 2) src = g_wl0 + (size_t)(n0 + r) * DD;
        else                src = g_wl1 + (size_t)(n0 + r) * DD;
        cp16(st + tile * KB_BYTES + r * 128 + ((seg ^ (r & 7)) << 4),
             src + kc * 64 + seg * 8);
    }
}

__global__ __launch_bounds__(256, 1) void k_impl_mma() {
    extern __shared__ char dsm[];
    const uint32_t sb = smem_u32(dsm);
    const int tid = threadIdx.x;
    const int lane = tid & 31;
    const int wid = tid >> 5;
    const int warp_m = wid >> 2;
    const int warp_n = wid & 3;
    const int m0 = blockIdx.x * 128;
    const int n0 = blockIdx.y * 128;
    const int gID = lane >> 2;
    const int tg  = lane & 3;

    const uint32_t aRow = (uint32_t)(warp_m * 64 + (lane & 15)) * 128;
    const uint32_t bRow = (uint32_t)(warp_n * 32 + ((lane >> 4) & 1) * 8 + (lane & 7)) * 128;
    const int lxor = lane & 7;

    float acc[4][4][4];
#pragma unroll
    for (int mt = 0; mt < 4; mt++)
#pragma unroll
        for (int nt = 0; nt < 4; nt++)
#pragma unroll
            for (int e = 0; e < 4; e++) acc[mt][nt][e] = 0.f;

    issue_impl(sb + 0 * (4 * KB_BYTES), m0, n0, 0, tid); CP_COMMIT();
    issue_impl(sb + 1 * (4 * KB_BYTES), m0, n0, 1, tid); CP_COMMIT();

    for (int kc = 0; kc < 8; kc++) {
        CP_WAIT1();
        __syncthreads();

        const uint32_t st = sb + (kc & 1) * (4 * KB_BYTES);
#pragma unroll
        for (int ks = 0; ks < 4; ks++) {
            const uint32_t aSw = (uint32_t)(((ks * 2 + (lane >> 4)) ^ lxor) << 4);
            const uint32_t bSw = (uint32_t)(((ks * 2 + ((lane >> 3) & 1)) ^ lxor) << 4);
            uint32_t aF[4][4], b0F[4][2], b1F[4][2];
#pragma unroll
            for (int mt = 0; mt < 4; mt++)
                LDM4(aF[mt][0], aF[mt][1], aF[mt][2], aF[mt][3],
                     st + 0 * KB_BYTES + aRow + mt * (16 * 128) + aSw);
#pragma unroll
            for (int p = 0; p < 2; p++) {
                uint32_t r0, r1, r2, r3;
                LDM4(r0, r1, r2, r3, st + 2 * KB_BYTES + bRow + p * (16 * 128) + bSw);
                b0F[2 * p][0] = r0; b0F[2 * p][1] = r1;
                b0F[2 * p + 1][0] = r2; b0F[2 * p + 1][1] = r3;
            }
#pragma unroll
            for (int mt = 0; mt < 4; mt++)
#pragma unroll
                for (int nt = 0; nt < 4; nt++) MMA16816(acc[mt][nt], aF[mt], b0F[nt]);
#pragma unroll
            for (int p = 0; p < 2; p++) {
                uint32_t r0, r1, r2, r3;
                LDM4(r0, r1, r2, r3, st + 3 * KB_BYTES + bRow + p * (16 * 128) + bSw);
                b1F[2 * p][0] = r0; b1F[2 * p][1] = r1;
                b1F[2 * p + 1][0] = r2; b1F[2 * p + 1][1] = r3;
            }
#pragma unroll
            for (int mt = 0; mt < 4; mt++)
#pragma unroll
                for (int nt = 0; nt < 4; nt++) MMA16816(acc[mt][nt], aF[mt], b1F[nt]);
#pragma unroll
            for (int mt = 0; mt < 4; mt++)
                LDM4(aF[mt][0], aF[mt][1], aF[mt][2], aF[mt][3],
                     st + 1 * KB_BYTES + aRow + mt * (16 * 128) + aSw);
#pragma unroll
            for (int mt = 0; mt < 4; mt++)
#pragma unroll
                for (int nt = 0; nt < 4; nt++) MMA16816(acc[mt][nt], aF[mt], b0F[nt]);
        }

        __syncthreads();
        const int kn = kc + 2;
        if (kn < 8)
            issue_impl(sb + (kn & 1) * (4 * KB_BYTES), m0, n0, kn, tid);
        CP_COMMIT();
    }

#pragma unroll
    for (int mt = 0; mt < 4; mt++) {
#pragma unroll
        for (int half = 0; half < 2; half++) {
            int row = m0 + warp_m * 64 + mt * 16 + gID + 8 * half;
#pragma unroll
            for (int nt = 0; nt < 4; nt++) {
                int col = n0 + warp_n * 32 + nt * 8 + tg * 2;
                float2 v = make_float2(acc[mt][nt][2 * half + 0],
                                       acc[mt][nt][2 * half + 1]);
                *(float2*)&g_implicit[(size_t)row * DD + col] = v;
            }
        }
    }
}

// ===========================================================================
// Kernel 3: k_prep_c — implicit row -> g_ch_sw + halfnorm. One warp/row.
// ===========================================================================
__global__ __launch_bounds__(256) void k_prep_c() {
    const int warp = threadIdx.x >> 5, lane = threadIdx.x & 31;
    const int row = blockIdx.x * 8 + warp;
    const int ct = row >> 7, lrow = row & 127;
    const float4* sr = (const float4*)(g_implicit + (size_t)row * DD);
    float s = 0.f;
#pragma unroll
    for (int it = 0; it < 2; it++) {
        int g16 = lane + 32 * it;              // 0..63
        int kc = g16 >> 4, rem = g16 & 15;
        int kb2 = rem >> 3, seg8 = rem & 7;
        float4 v0 = sr[g16 * 2 + 0];
        float4 v1 = sr[g16 * 2 + 1];
        s += v0.x * v0.x + v0.y * v0.y + v0.z * v0.z + v0.w * v0.w;
        s += v1.x * v1.x + v1.y * v1.y + v1.z * v1.z + v1.w * v1.w;
        __half L[8] = {__float2half_rn(v0.x), __float2half_rn(v0.y),
                       __float2half_rn(v0.z), __float2half_rn(v0.w),
                       __float2half_rn(v1.x), __float2half_rn(v1.y),
                       __float2half_rn(v1.z), __float2half_rn(v1.w)};
        size_t off = ((size_t)((ct * 4 + kc) * 2 + kb2)) * KB_BYTES
                   + lrow * 128 + ((seg8 ^ (lrow & 7)) << 4);
        *(uint4*)(g_ch_sw + off) = *(uint4*)L;
    }
#pragma unroll
    for (int o = 16; o > 0; o >>= 1) s += __shfl_xor_sync(0xffffffff, s, o);
    if (lane == 0) g_halfnorm[row] = 0.5f * s;
}

// ===========================================================================
// Kernel 4: HMMA screening GEMM, 8 warps, 64x32 tiles, bulk loads,
// software-pipelined fragment double-buffering (ldsm step+1 under MMA step).
// ===========================================================================
__global__ __launch_bounds__(SCR_THR, 1) void k_screen_mma() {
    extern __shared__ char dsm[];
    __shared__ uint32_t sv[4][128][4];
    __shared__ __align__(8) unsigned long long mbar_store[2];

    const uint32_t sa = smem_u32(dsm);            // A resident, 128KB
    const uint32_t sbB = sa + A_BYTES;            // B stages (2 x 32KB)
    const uint32_t MB = smem_u32(mbar_store);
    const int tid = threadIdx.x;
    const int lane = tid & 31;
    const int wid = tid >> 5;
    const int warp_m = wid >> 2;      // 0..1  (64 rows each)
    const int warp_n = wid & 3;       // 0..3  (32 cols each)
    const int m0 = blockIdx.x * Bb_M;
    const int gID = lane >> 2;
    const int tg  = lane & 3;

    const uint32_t aRow = (uint32_t)(warp_m * 64 + (lane & 15)) * 128;
    const uint32_t bRow = (uint32_t)(warp_n * 32 + ((lane >> 4) & 1) * 8 + (lane & 7)) * 128;
    const int lxor = lane & 7;

    // per-step swizzle offsets (ks = step & 3), computed once
    uint32_t aSwT[4], bSwT[4];
#pragma unroll
    for (int ks = 0; ks < 4; ks++) {
        aSwT[ks] = (uint32_t)(((ks * 2 + (lane >> 4)) ^ lxor) << 4);
        bSwT[ks] = (uint32_t)(((ks * 2 + ((lane >> 3) & 1)) ^ lxor) << 4);
    }

    uint32_t t2[4][2][2];
#pragma unroll
    for (int mt = 0; mt < 4; mt++)
#pragma unroll
        for (int h = 0; h < 2; h++) { t2[mt][h][0] = 0xFFFFFFFFu; t2[mt][h][1] = 0xFFFFFFFFu; }

    float acc[4][4][4];
    uint32_t aF[2][4][4], bF[2][4][2];

    if (tid == 0) {
        mbar_init(MB + 0, 1);
        mbar_init(MB + 8, 1);
    }
    __syncthreads();

    if (tid == 0) {
        mbar_expect_tx(MB + 0, A_BYTES + BSTAGE_BYTES);
        bulk_copy(sa, g_xh_sw + (size_t)blockIdx.x * A_BYTES, A_BYTES, MB + 0);
        bulk_copy(sbB + 0 * BSTAGE_BYTES, g_ch_sw + 0 * (size_t)BSTAGE_BYTES,
                  BSTAGE_BYTES, MB + 0);
        mbar_expect_tx(MB + 8, BSTAGE_BYTES);
        bulk_copy(sbB + 1 * BSTAGE_BYTES, g_ch_sw + 1 * (size_t)BSTAGE_BYTES,
                  BSTAGE_BYTES, MB + 8);
    }

    int fph[2] = {0, 0};

    for (int q = 0; q < NQ; q++) {
        const int ct = q >> 2;
        const int kc = q & 3;
        const int s = q & 1;

        mbar_wait(MB + s * 8, fph[s]);
        fph[s] ^= 1;

        if (kc == 0) {
#pragma unroll
            for (int mt = 0; mt < 4; mt++)
#pragma unroll
                for (int nt = 0; nt < 4; nt++)
#pragma unroll
                    for (int e = 0; e < 4; e++) acc[mt][nt][e] = 0.f;
        }

        const uint32_t bStage = sbB + s * BSTAGE_BYTES;

        // ---- software-pipelined 8 steps (kb2 = step>>2, ks = step&3) ----
        // load step 0 into buffer 0
        {
            const uint32_t aBase = sa + (kc * 2 + 0) * KB_BYTES;
            const uint32_t bBase = bStage + 0 * KB_BYTES;
#pragma unroll
            for (int mt = 0; mt < 4; mt++)
                LDM4(aF[0][mt][0], aF[0][mt][1], aF[0][mt][2], aF[0][mt][3],
                     aBase + aRow + mt * (16 * 128) + aSwT[0]);
#pragma unroll
            for (int p = 0; p < 2; p++) {
                uint32_t r0, r1, r2, r3;
                LDM4(r0, r1, r2, r3, bBase + bRow + p * (16 * 128) + bSwT[0]);
                bF[0][2 * p][0] = r0; bF[0][2 * p][1] = r1;
                bF[0][2 * p + 1][0] = r2; bF[0][2 * p + 1][1] = r3;
            }
        }
#pragma unroll
        for (int step = 0; step < 8; step++) {
            const int cur = step & 1;
            if (step < 7) {
                const int ns = step + 1;
                const int nkb2 = ns >> 2, nks = ns & 3;
                const uint32_t aBase = sa + (kc * 2 + nkb2) * KB_BYTES;
                const uint32_t bBase = bStage + nkb2 * KB_BYTES;
                const int nxt = cur ^ 1;
#pragma unroll
                for (int mt = 0; mt < 4; mt++)
                    LDM4(aF[nxt][mt][0], aF[nxt][mt][1], aF[nxt][mt][2], aF[nxt][mt][3],
                         aBase + aRow + mt * (16 * 128) + aSwT[nks]);
#pragma unroll
                for (int p = 0; p < 2; p++) {
                    uint32_t r0, r1, r2, r3;
                    LDM4(r0, r1, r2, r3, bBase + bRow + p * (16 * 128) + bSwT[nks]);
                    bF[nxt][2 * p][0] = r0; bF[nxt][2 * p][1] = r1;
                    bF[nxt][2 * p + 1][0] = r2; bF[nxt][2 * p + 1][1] = r3;
                }
            }
#pragma unroll
            for (int mt = 0; mt < 4; mt++)
#pragma unroll
                for (int nt = 0; nt < 4; nt++)
                    MMA16816(acc[mt][nt], aF[cur][mt], bF[cur][nt]);
        }

        if (kc == 3) {
            float2 hn[4];
#pragma unroll
            for (int nt = 0; nt < 4; nt++)
                hn[nt] = *(const float2*)&g_halfnorm[ct * Bb_N + warp_n * 32 + nt * 8 + tg * 2];

#pragma unroll
            for (int mt = 0; mt < 4; mt++) {
#pragma unroll
                for (int half = 0; half < 2; half++) {
#pragma unroll
                    for (int nt = 0; nt < 4; nt++) {
                        int cbase = ct * Bb_N + warp_n * 32 + nt * 8 + tg * 2;
                        float s0 = hn[nt].x - acc[mt][nt][2 * half + 0];
                        float s1 = hn[nt].y - acc[mt][nt][2 * half + 1];
                        ins2u((fkey(s0) & 0xFFFFF000u) | (uint32_t)cbase,
                              t2[mt][half][0], t2[mt][half][1]);
                        ins2u((fkey(s1) & 0xFFFFF000u) | (uint32_t)(cbase + 1),
                              t2[mt][half][0], t2[mt][half][1]);
                    }
                }
            }
        }

        __syncthreads();
        const int qn = q + 2;
        if (qn < NQ && tid == 0) {
            mbar_expect_tx(MB + s * 8, BSTAGE_BYTES);
            bulk_copy(sbB + s * BSTAGE_BYTES,
                      g_ch_sw + (size_t)qn * BSTAGE_BYTES, BSTAGE_BYTES, MB + s * 8);
        }
    }

    // ---- one-time merge ----
#pragma unroll
    for (int mt = 0; mt < 4; mt++) {
#pragma unroll
        for (int half = 0; half < 2; half++) {
            uint32_t b0 = t2[mt][half][0], b1 = t2[mt][half][1];
            uint32_t b2 = 0xFFFFFFFFu, b3 = 0xFFFFFFFFu;
#pragma unroll
            for (int off = 1; off <= 2; off <<= 1) {
                uint32_t o0 = __shfl_xor_sync(0xffffffff, b0, off);
                uint32_t o1 = __shfl_xor_sync(0xffffffff, b1, off);
                uint32_t o2 = __shfl_xor_sync(0xffffffff, b2, off);
                uint32_t o3 = __shfl_xor_sync(0xffffffff, b3, off);
                ins4u(o0, b0, b1, b2, b3);
                ins4u(o1, b0, b1, b2, b3);
                ins4u(o2, b0, b1, b2, b3);
                ins4u(o3, b0, b1, b2, b3);
            }
            if (tg == 0) {
                int r = warp_m * 64 + mt * 16 + gID + 8 * half;
                sv[warp_n][r][0] = b0; sv[warp_n][r][1] = b1;
                sv[warp_n][r][2] = b2; sv[warp_n][r][3] = b3;
            }
        }
    }
    __syncthreads();
    if (tid < 128) {
        uint32_t rb0 = 0xFFFFFFFFu, rb1 = 0xFFFFFFFFu, rb2 = 0xFFFFFFFFu, rb3 = 0xFFFFFFFFu;
#pragma unroll
        for (int wn = 0; wn < 4; wn++) {
            ins4u(sv[wn][tid][0], rb0, rb1, rb2, rb3);
            ins4u(sv[wn][tid][1], rb0, rb1, rb2, rb3);
            ins4u(sv[wn][tid][2], rb0, rb1, rb2, rb3);
            ins4u(sv[wn][tid][3], rb0, rb1, rb2, rb3);
        }
        int gm = m0 + tid;
        g_cand[gm * 4 + 0] = (int)(rb0 & 0xFFFu);
        g_cand[gm * 4 + 1] = (int)(rb1 & 0xFFFu);
        g_cand[gm * 4 + 2] = (int)(rb2 & 0xFFFu);
        g_cand[gm * 4 + 3] = (int)(rb3 & 0xFFFu);
    }
}

// ===========================================================================
// Kernel 5: fused exact rescore (4 candidates) + rotation. One block per row.
// ===========================================================================
__global__ __launch_bounds__(128) void k_rescore_rot(const float* __restrict__ X,
                                                     float* __restrict__ outq,
                                                     float* __restrict__ out_idx_f) {
    __shared__ float xs[DD];
    __shared__ float cscore[4];
    __shared__ int   cidx[4];
    __shared__ float red[4][4];

    const int m = blockIdx.x;
    const int t = threadIdx.x;
    const int warp = t >> 5, lane = t & 31;
    const float* xr = X + (size_t)m * DD;

    float4 xv = ((const float4*)xr)[t];
    ((float4*)xs)[t] = xv;
    __syncthreads();

    {
        int ci = g_cand[m * 4 + warp];
        const float4* cr = (const float4*)(g_implicit + (size_t)ci * DD);
        float dot = 0.f;
#pragma unroll
        for (int t2 = 0; t2 < 4; t2++) {
            float4 cv = cr[lane + 32 * t2];
            float4 x4 = ((const float4*)xs)[lane + 32 * t2];
            dot += x4.x * cv.x + x4.y * cv.y + x4.z * cv.z + x4.w * cv.w;
        }
#pragma unroll
        for (int o = 16; o > 0; o >>= 1) dot += __shfl_xor_sync(0xffffffff, dot, o);
        if (lane == 0) {
            cscore[warp] = g_halfnorm[ci] - dot;
            cidx[warp] = ci;
        }
    }
    __syncthreads();

    float bv = cscore[0]; int bi = cidx[0];
#pragma unroll
    for (int k = 1; k < 4; k++) {
        float v = cscore[k]; int ci = cidx[k];
        if (v < bv || (v == bv && ci < bi)) { bv = v; bi = ci; }
    }
    if (t == 0) out_idx_f[m] = (float)bi;

    const float* qr = g_implicit + (size_t)bi * DD;
    float4 qv = ((const float4*)qr)[t];

    float sx  = xv.x * xv.x + xv.y * xv.y + xv.z * xv.z + xv.w * xv.w;
    float sq  = qv.x * qv.x + qv.y * qv.y + qv.z * qv.z + qv.w * qv.w;
    float sxq = xv.x * qv.x + xv.y * qv.y + xv.z * qv.z + xv.w * qv.w;
    float d0 = xv.x - qv.x + 1e-6f, d1 = xv.y - qv.y + 1e-6f;
    float d2 = xv.z - qv.z + 1e-6f, d3 = xv.w - qv.w + 1e-6f;
    float sc = d0 * d0 + d1 * d1 + d2 * d2 + d3 * d3;

#pragma unroll
    for (int o = 16; o > 0; o >>= 1) {
        sx  += __shfl_xor_sync(0xffffffff, sx, o);
        sq  += __shfl_xor_sync(0xffffffff, sq, o);
        sxq += __shfl_xor_sync(0xffffffff, sxq, o);
        sc  += __shfl_xor_sync(0xffffffff, sc, o);
    }
    if (lane == 0) { red[warp][0] = sx; red[warp][1] = sq; red[warp][2] = sxq; red[warp][3] = sc; }
    __syncthreads();
    sx  = red[0][0] + red[1][0] + red[2][0] + red[3][0];
    sq  = red[0][1] + red[1][1] + red[2][1] + red[3][1];
    sxq = red[0][2] + red[1][2] + red[2][2] + red[3][2];
    sc  = red[0][3] + red[1][3] + red[2][3] + red[3][3];

    if (t == 0) g_commit[m] = sc;

    float norm_x = sqrtf(sx), norm_q = sqrtf(sq);
    float nx = fmaxf(norm_x, 1e-6f);
    float nq = fmaxf(norm_q, 1e-6f);
    float uq2 = sx / (nx * nx) + sq / (nq * nq) + 2.f * sxq / (nx * nq);
    float nuq = sqrtf(fmaxf(uq2, 0.f));
    float wden = fmaxf(nuq, 1e-12f);
    float e_w = (sx / nx + sxq / nq) / wden;
    float e_u = sx / nx;
    float c1 = 2.f * e_w / wden;
    float c2 = 2.f * e_u;
    float scale = norm_q / nx;
    float coef_x = (1.f - c1 / nx) * scale;
    float coef_q = ((c2 - c1) / nq) * scale;

    float4 ov;
    ov.x = coef_x * xv.x + coef_q * qv.x;
    ov.y = coef_x * xv.y + coef_q * qv.y;
    ov.z = coef_x * xv.z + coef_q * qv.z;
    ov.w = coef_x * xv.w + coef_q * qv.w;
    ((float4*)(outq + (size_t)m * DD))[t] = ov;
}

// ===========================================================================
// Kernel 6: deterministic loss reduction
// ===========================================================================
__global__ __launch_bounds__(256) void k_loss(float* __restrict__ out_loss) {
    __shared__ float s[256];
    float v = 0.f;
    for (int i = threadIdx.x; i < MM; i += 256) v += g_commit[i];
    s[threadIdx.x] = v;
    __syncthreads();
    for (int o = 128; o > 0; o >>= 1) {
        if (threadIdx.x < o) s[threadIdx.x] += s[threadIdx.x + o];
        __syncthreads();
    }
    if (threadIdx.x == 0) out_loss[0] = s[0] / (float)MM;
}

// ===========================================================================
extern "C" void kernel_launch(void* const* d_in, const int* in_sizes, int n_in,
                              void* d_out, int out_size) {
    const float* x  = (const float*)d_in[0];
    const float* cb = (const float*)d_in[1];
    const float* Wm = (const float*)d_in[2];
    float* out = (float*)d_out;

    int idx_off  = out_size - MM - 1;
    int loss_off = out_size - 1;

    static bool attr_done = false;
    if (!attr_done) {
        cudaFuncSetAttribute(k_screen_mma, cudaFuncAttributeMaxDynamicSharedMemorySize, SMEM_DYN);
        cudaFuncSetAttribute(k_impl_mma, cudaFuncAttributeMaxDynamicSharedMemorySize, SMEM_IMPL);
        attr_done = true;
    }

    k_prep_all<<<(MM + CC + DD) / 8, 256>>>(x, cb, Wm);
    k_impl_mma<<<dim3(CC / 128, DD / 128), 256, SMEM_IMPL>>>();
    k_prep_c<<<CC / 8, 256>>>();
    k_screen_mma<<<MM / Bb_M, SCR_THR, SMEM_DYN>>>();
    k_rescore_rot<<<MM, 128>>>(x, out, out + idx_off);
    k_loss<<<1, 256>>>(out + loss_off);
}